// round 9
// baseline (speedup 1.0000x reference)
#include <cuda_runtime.h>
#include <cstdint>

// ---------------- Problem constants ----------------
#define E_TOTAL   500000
#define TILE_M    64
#define NTILES    ((E_TOTAL + TILE_M - 1) / TILE_M)   // 7813
#define NTHREADS  256

// ---------------- SMEM layout (bytes) ----------------
// W: 5 chunks, each [64 n x 64 k] tf32 = 16KB -> 80KB (loaded once per CTA)
// A: 2 chunk buffers [64 rows x 64 k] tf32 = 16KB each
#define SM_W       0
#define SM_B0      (5 * 16384)             // 81920
#define SM_B1      (SM_B0 + 16384)         // 98304
#define SMEM_TOTAL (SM_B1 + 16384)         // 114688 = 112KB -> 2 CTAs/SM

// ---------------- helpers ----------------
__device__ __forceinline__ uint32_t smem_u32(const void* p) {
    uint32_t a;
    asm("{ .reg .u64 t; cvta.to.shared.u64 t, %1; cvt.u32.u64 %0, t; }"
        : "=r"(a) : "l"(p));
    return a;
}

__device__ __forceinline__ uint32_t f2tf32(float f) {
    uint32_t r;
    asm("cvt.rna.tf32.f32 %0, %1;" : "=r"(r) : "f"(f));
    return r;
}

// Tile layout: [rows x 64 cols] tf32, 256B/row, cols k-permuted per 16-col
// group: quad (grp,t) holds cols {16grp+t, +4, +8, +12}.
// Swizzle: XOR byte bits[6:4] with sw(row)=((row&1)<<2)|(row&2)|((row>>2)&1).
__device__ __forceinline__ uint32_t tileoff(int row, int grp, int t) {
    uint32_t o  = (uint32_t)(row * 256 + grp * 64 + t * 16);
    uint32_t sw = (((uint32_t)row & 1u) << 2) | ((uint32_t)row & 2u) |
                  (((uint32_t)row >> 2) & 1u);
    return o ^ (sw << 4);
}

__device__ __forceinline__ void sts128(uint32_t addr, uint32_t a, uint32_t b,
                                       uint32_t c, uint32_t d) {
    asm volatile("st.shared.v4.b32 [%0], {%1,%2,%3,%4};"
                 :: "r"(addr), "r"(a), "r"(b), "r"(c), "r"(d) : "memory");
}

__device__ __forceinline__ void lds128(uint32_t addr, uint32_t* r) {
    asm volatile("ld.shared.v4.b32 {%0,%1,%2,%3}, [%4];"
                 : "=r"(r[0]), "=r"(r[1]), "=r"(r[2]), "=r"(r[3])
                 : "r"(addr));
}

__device__ __forceinline__ void mma_tf32(float* c, uint32_t a0, uint32_t a1,
                                         uint32_t a2, uint32_t a3,
                                         uint32_t b0, uint32_t b1) {
    asm volatile(
        "mma.sync.aligned.m16n8k8.row.col.f32.tf32.tf32.f32 "
        "{%0,%1,%2,%3},{%4,%5,%6,%7},{%8,%9},{%0,%1,%2,%3};"
        : "+f"(c[0]), "+f"(c[1]), "+f"(c[2]), "+f"(c[3])
        : "r"(a0), "r"(a1), "r"(a2), "r"(a3), "r"(b0), "r"(b1));
}

// 4x4 transpose across 4 consecutive lanes (sub = lane&3), in-place.
__device__ __forceinline__ void transpose4(float4& v, int sub) {
    float t0 = (sub & 1) ? v.x : v.y;
    float t1 = (sub & 1) ? v.z : v.w;
    t0 = __shfl_xor_sync(0xffffffffu, t0, 1);
    t1 = __shfl_xor_sync(0xffffffffu, t1, 1);
    if (sub & 1) { v.x = t0; v.z = t1; } else { v.y = t0; v.w = t1; }
    float t2 = (sub & 2) ? v.x : v.z;
    float t3 = (sub & 2) ? v.y : v.w;
    t2 = __shfl_xor_sync(0xffffffffu, t2, 2);
    t3 = __shfl_xor_sync(0xffffffffu, t3, 2);
    if (sub & 2) { v.x = t2; v.y = t3; } else { v.z = t2; v.w = t3; }
}

// In-thread repack for W staging (thread holds all 4 quads of one group).
__device__ __forceinline__ void sts_group_w(uint32_t base, int row, int grp,
                                            const float4* v) {
    const float* f = (const float*)v;
#pragma unroll
    for (int t = 0; t < 4; t++) {
        sts128(base + tileoff(row, grp, t),
               f2tf32(f[0 * 4 + t]), f2tf32(f[1 * 4 + t]),
               f2tf32(f[2 * 4 + t]), f2tf32(f[3 * 4 + t]));
    }
}

// ---- cooperative gather/store streams: warp = 8 edges, 4 passes of 2 ----
// Lane: q = lid&15 (quad in 256B row), half = lid>>4 (edge parity).
__device__ __forceinline__ void gather_x4(const float* __restrict__ x, int base,
                                          int q, int half, float4* D) {
#pragma unroll
    for (int k = 0; k < 4; k++) {
        int e = base + 2 * k + half;
        if (e > E_TOTAL - 1) e = E_TOTAL - 1;
        D[k] = __ldg((const float4*)x + (size_t)e * 16 + q);
    }
}

// comp: lanes 0..7 hold the neighbor index for edge we0+lane.
__device__ __forceinline__ void gather_nbr4(const float* __restrict__ x, int comp,
                                            int q, int half, float4* D) {
#pragma unroll
    for (int k = 0; k < 4; k++) {
        int idx = __shfl_sync(0xffffffffu, comp, 2 * k + half);
        float4 v = make_float4(0.f, 0.f, 0.f, 0.f);
        if (idx >= 0) v = __ldg((const float4*)x + (size_t)idx * 16 + q);
        D[k] = v;
    }
}

__device__ __forceinline__ void minmax4(float4* a, float4* b) {
#pragma unroll
    for (int i = 0; i < 4; i++) {
        float4 u = a[i], v = b[i];
        a[i] = make_float4(fminf(u.x, v.x), fminf(u.y, v.y),
                           fminf(u.z, v.z), fminf(u.w, v.w));
        b[i] = make_float4(fmaxf(u.x, v.x), fmaxf(u.y, v.y),
                           fmaxf(u.z, v.z), fmaxf(u.w, v.w));
    }
}

// Transpose (cross-lane) + convert + STS one stream of 4 edge-pairs.
__device__ __forceinline__ void xpose_sts4(uint32_t buf, int we0, int half,
                                           int grp, int sub, const float4* S) {
#pragma unroll
    for (int k = 0; k < 4; k++) {
        float4 v = S[k];
        transpose4(v, sub);
        int row = we0 + 2 * k + half;
        sts128(buf + tileoff(row, grp, sub),
               f2tf32(v.x), f2tf32(v.y), f2tf32(v.z), f2tf32(v.w));
    }
}

// One K=64 chunk of MMA for this warp's m16 x n32 block.
__device__ __forceinline__ void mma_chunk(uint32_t aB, uint32_t wB, int wm,
                                          int wn, int g, int tig,
                                          float acc[4][4]) {
#pragma unroll
    for (int t = 0; t < 4; t++) {
        uint32_t Bf[4][4];
#pragma unroll
        for (int nf = 0; nf < 4; nf++)
            lds128(wB + tileoff(wn * 32 + nf * 8 + g, t, tig), Bf[nf]);
        uint32_t Af[2][4];
#pragma unroll
        for (int rh = 0; rh < 2; rh++)
            lds128(aB + tileoff(wm * 16 + rh * 8 + g, t, tig), Af[rh]);
#pragma unroll
        for (int nf = 0; nf < 4; nf++)
#pragma unroll
            for (int s = 0; s < 2; s++)
                mma_tf32(acc[nf],
                         Af[0][2 * s], Af[1][2 * s],
                         Af[0][2 * s + 1], Af[1][2 * s + 1],
                         Bf[nf][2 * s], Bf[nf][2 * s + 1]);
    }
}

// ---------------- kernel ----------------
// K=320 chunks: c0:x c1:min01 c2:max01 c3:min23 c4:max23
// TILE_M=64, 2 CTAs/SM (112KB smem each). 8 warps, uniform roles:
// producer: warp owns 8 edges; consumer: warp tile m16 x n32 (4m x 2n).
__global__ void __launch_bounds__(NTHREADS, 2)
meshconv_kernel(const float* __restrict__ x, const int* __restrict__ nbr,
                const float* __restrict__ W, const float* __restrict__ bias,
                float* __restrict__ out) {
    extern __shared__ char smem[];
    const uint32_t sb = smem_u32(smem);
    const int tid = threadIdx.x;
    const int lid = tid & 31, wid = tid >> 5;
    // consumer identity
    const int wm = wid & 3, wn = wid >> 2;
    const int g = lid >> 2, tig = lid & 3;
    // producer identity
    const int q = lid & 15, half = lid >> 4, sub = lid & 3, grp = q >> 2;
    const int we0 = wid * 8;

    const uint32_t b0 = sb + SM_B0, b1 = sb + SM_B1;

    // ---- stage W once ----
#pragma unroll
    for (int c = 0; c < 5; c++) {
        int n = tid & 63;
        int gw = tid >> 6;
        float4 v[4];
#pragma unroll
        for (int i = 0; i < 4; i++)
            v[i] = ((const float4*)W)[(size_t)n * 80 + c * 16 + gw * 4 + i];
        sts_group_w(sb + SM_W + (uint32_t)c * 16384u, n, gw, v);
    }

    // bias fragment
    float bv[4][2];
#pragma unroll
    for (int nf = 0; nf < 4; nf++) {
        int bc = wn * 32 + nf * 8 + tig * 2;
        bv[nf][0] = __ldg(bias + bc);
        bv[nf][1] = __ldg(bias + bc + 1);
    }

    // ---- prologue gathers for first tile ----
    int tile = blockIdx.x;
    int base = tile * TILE_M + we0;
    int4 NB = make_int4(-1, -1, -1, -1);
    {
        int e = base + (lid & 7);
        if (e > E_TOTAL - 1) e = E_TOTAL - 1;
        if (lid < 8) NB = __ldg((const int4*)nbr + e);
    }
    float4 XQ[4];
    gather_x4(x, base, q, half, XQ);
    float4 A0[4], B0[4];
    gather_nbr4(x, NB.x, q, half, A0);
    gather_nbr4(x, NB.y, q, half, B0);

    __syncthreads();   // W staged

    for (; tile < NTILES; tile += gridDim.x) {
        int tn = tile + gridDim.x;
        if (tn >= NTILES) tn = tile;
        const int nbase = tn * TILE_M + we0;

        float acc[4][4];
#pragma unroll
        for (int b = 0; b < 4; b++)
#pragma unroll
            for (int k = 0; k < 4; k++) acc[b][k] = 0.f;

        // s-1: STS c0 (x) -> b0
        xpose_sts4(b0, we0, half, grp, sub, XQ);
        __syncthreads();

        // s0: issue A1; minmax pair0; STS c1(min01)->b1; mma c0(b0)
        float4 A1[4], B1[4];
        gather_nbr4(x, NB.z, q, half, A1);
        minmax4(A0, B0);
        xpose_sts4(b1, we0, half, grp, sub, A0);
        mma_chunk(b0, sb + SM_W + 0 * 16384u, wm, wn, g, tig, acc);
        __syncthreads();

        // s1: issue B1; STS c2(max01)->b0; mma c1(b1)
        gather_nbr4(x, NB.w, q, half, B1);
        xpose_sts4(b0, we0, half, grp, sub, B0);
        mma_chunk(b1, sb + SM_W + 1 * 16384u, wm, wn, g, tig, acc);
        __syncthreads();

        // s2: minmax pair1; STS c3(min23)->b1; prefetch next x + nbr; mma c2(b0)
        minmax4(A1, B1);
        xpose_sts4(b1, we0, half, grp, sub, A1);
        gather_x4(x, nbase, q, half, XQ);
        int4 NBn = make_int4(-1, -1, -1, -1);
        {
            int e = nbase + (lid & 7);
            if (e > E_TOTAL - 1) e = E_TOTAL - 1;
            if (lid < 8) NBn = __ldg((const int4*)nbr + e);
        }
        mma_chunk(b0, sb + SM_W + 2 * 16384u, wm, wn, g, tig, acc);
        __syncthreads();

        // s3: STS c4(max23)->b0; issue next A0; mma c3(b1)
        xpose_sts4(b0, we0, half, grp, sub, B1);
        gather_nbr4(x, NBn.x, q, half, A0);
        mma_chunk(b1, sb + SM_W + 3 * 16384u, wm, wn, g, tig, acc);
        __syncthreads();

        // s4: mma c4(b0); issue next B0; epilogue
        mma_chunk(b0, sb + SM_W + 4 * 16384u, wm, wn, g, tig, acc);
        gather_nbr4(x, NBn.y, q, half, B0);
        NB = NBn;

#pragma unroll
        for (int nf = 0; nf < 4; nf++) {
            const int e0  = tile * TILE_M + wm * 16 + g;
            const int e1  = e0 + 8;
            const int col = wn * 32 + nf * 8 + tig * 2;
            if (e0 < E_TOTAL) {
                float2 o;
                o.x = acc[nf][0] + bv[nf][0];
                o.y = acc[nf][1] + bv[nf][1];
                *(float2*)(out + (size_t)e0 * 64 + col) = o;
            }
            if (e1 < E_TOTAL) {
                float2 o;
                o.x = acc[nf][2] + bv[nf][0];
                o.y = acc[nf][3] + bv[nf][1];
                *(float2*)(out + (size_t)e1 * 64 + col) = o;
            }
        }
        __syncthreads();   // protect b0 before next tile's STS c0
    }
}

// ---------------- launch ----------------
extern "C" void kernel_launch(void* const* d_in, const int* in_sizes, int n_in,
                              void* d_out, int out_size) {
    const float* x   = (const float*)d_in[0];
    const int*   nbr = (const int*)d_in[1];
    const float* W   = (const float*)d_in[2];
    const float* b   = (const float*)d_in[3];
    float* out = (float*)d_out;

    int nsm = 0;
    cudaDeviceGetAttribute(&nsm, cudaDevAttrMultiProcessorCount, 0);
    if (nsm <= 0) nsm = 148;

    cudaFuncSetAttribute(meshconv_kernel,
                         cudaFuncAttributeMaxDynamicSharedMemorySize, SMEM_TOTAL);
    meshconv_kernel<<<2 * nsm, NTHREADS, SMEM_TOTAL>>>(x, nbr, W, b, out);
}